// round 17
// baseline (speedup 1.0000x reference)
#include <cuda_runtime.h>
#include <cstdint>

// Problem constants (fixed by setup_inputs)
#define BATCH   8
#define LEN     4096
#define ROWS    (BATCH * LEN)      // 32768
#define NST     256                // state/input/output size
#define KHALF   128                // number of 2x2 complex channels
#define LC      64                 // scan chunk length == GEMM block M tile
#define CHUNKS  (ROWS / LC)        // 512
#define CPB     (LEN / LC)         // 64 chunks per batch sequence

// Scratch (device globals: no allocation allowed)
__device__ float g_x1[ROWS * NST];     // u @ B (f32)
__device__ float g_s [CHUNKS * NST];   // per-chunk local scan results
__device__ float g_in[CHUNKS * NST];   // per-chunk incoming states
__device__ float g_Bt[NST * NST];      // B^T, tf32(rna)  [n][k]
__device__ float g_Ct[NST * NST];      // C^T, tf32(rna)  [n][k]

// ---------------------------------------------------------------------------
// helpers
// ---------------------------------------------------------------------------
__device__ __forceinline__ uint32_t f2tf(float f) {
    uint32_t r;
    asm("cvt.rna.tf32.f32 %0, %1;" : "=r"(r) : "f"(f));
    return r;
}

__device__ __forceinline__ void mma4(float* d, const uint32_t* a, uint32_t b0, uint32_t b1) {
    asm volatile(
        "mma.sync.aligned.m16n8k8.row.col.f32.tf32.tf32.f32 "
        "{%0,%1,%2,%3}, {%4,%5,%6,%7}, {%8,%9}, {%0,%1,%2,%3};\n"
        : "+f"(d[0]), "+f"(d[1]), "+f"(d[2]), "+f"(d[3])
        : "r"(a[0]), "r"(a[1]), "r"(a[2]), "r"(a[3]), "r"(b0), "r"(b1));
}

__device__ __forceinline__ void ldsm4(uint32_t* r, uint32_t addr) {
    asm volatile("ldmatrix.sync.aligned.m8n8.x4.shared.b16 {%0,%1,%2,%3}, [%4];"
                 : "=r"(r[0]), "=r"(r[1]), "=r"(r[2]), "=r"(r[3]) : "r"(addr));
}

__device__ __forceinline__ void cp16(uint32_t smem, const void* gmem) {
    asm volatile("cp.async.ca.shared.global [%0], [%1], 16;\n" :: "r"(smem), "l"(gmem));
}
__device__ __forceinline__ void cp_commit() {
    asm volatile("cp.async.commit_group;\n");
}
__device__ __forceinline__ void cp_wait0() {
    asm volatile("cp.async.wait_group 0;\n");
}
__device__ __forceinline__ void cp_wait1() {
    asm volatile("cp.async.wait_group 1;\n");
}

// ===========================================================================
// prep: weights -> transposed tf32(rna) copies.
// ===========================================================================
__global__ void prep_wt(const float* __restrict__ B, const float* __restrict__ C) {
    int i = blockIdx.x * blockDim.x + threadIdx.x;   // i = k*256 + n
    int k = i >> 8, n = i & 255;
    g_Bt[n * NST + k] = __uint_as_float(f2tf(B[i]));
    g_Ct[n * NST + k] = __uint_as_float(f2tf(C[i]));
}

// ===========================================================================
// K1: gemm1 (x1 = u @ B) fused with per-chunk zero-init local scan -> g_s.
// 128 threads / 4 warps, block tile 64x256, warp tile 64x64, BK=16.
// A (u, DRAM): 3-stage cp.async (2-iter cover); B^T (L2-hot): 2-stage.
// Per-iter commit order: B(it+1) then A(it+2); wait_group 1 keeps only the
// newest (A) group pending. A fragments cvt.rna'd in registers post-ldmatrix.
// SMEM: As[3][64][20] (15360) + Bs[2][256][20] (40960) = 56320;
//       xs alias 64x258 = 66048  ->  3 blocks/SM.
// ===========================================================================
__global__ void __launch_bounds__(128, 3) gemm_scan1(const float* __restrict__ u,
                                                     const float* __restrict__ Arot)
{
    extern __shared__ float sm1[];
    float (*As)[64][20]  = (float(*)[64][20])sm1;            // [3][64][20]
    float (*Bs)[256][20] = (float(*)[256][20])(sm1 + 3840);  // [2][256][20]
    float (*xs)[258]     = (float(*)[258])sm1;               // alias (epilogue)

    const int tid  = threadIdx.x;
    const int warp = tid >> 5;
    const int lane = tid & 31;
    const int g = lane >> 2, t = lane & 3;
    const long mbase = (long)blockIdx.x * 64;
    const int nb0 = warp * 64;

    const int aRow = (lane & 7) + ((lane >> 3) & 1) * 8;
    const int aCol = (lane >> 4) * 4;
    const int bRow = (lane & 7) + (lane >> 4) * 8;
    const int bCol = ((lane >> 3) & 1) * 4;

    auto commitA = [&](int k0, int st) {
        #pragma unroll
        for (int p = 0; p < 2; ++p) {
            int ch = tid + p * 128;
            int r = ch >> 2, c4 = (ch & 3) * 4;
            cp16((uint32_t)__cvta_generic_to_shared(&As[st][r][c4]),
                 u + (mbase + r) * NST + k0 + c4);
        }
        cp_commit();
    };
    auto commitB = [&](int k0, int st) {
        #pragma unroll
        for (int p = 0; p < 8; ++p) {
            int ch = tid + p * 128;
            int n = ch >> 2, c4 = (ch & 3) * 4;
            cp16((uint32_t)__cvta_generic_to_shared(&Bs[st][n][c4]),
                 g_Bt + n * NST + k0 + c4);
        }
        cp_commit();
    };

    float acc[4][8][4];
    #pragma unroll
    for (int i = 0; i < 4; ++i)
        #pragma unroll
        for (int j = 0; j < 8; ++j)
            #pragma unroll
            for (int q = 0; q < 4; ++q) acc[i][j][q] = 0.f;

    // prologue groups: gA0, gB0, gA1
    commitA(0, 0);
    commitB(0, 0);
    commitA(16, 1);

    int abuf = 0;
    for (int it = 0; it < 16; ++it) {
        if (it == 15) cp_wait0(); else cp_wait1();
        __syncthreads();
        if (it + 1 < 16) commitB((it + 1) * 16, (it + 1) & 1);
        if (it + 2 < 16) commitA((it + 2) * 16, (it + 2) % 3);

        const uint32_t sA = (uint32_t)__cvta_generic_to_shared(&As[abuf][0][0]);
        const uint32_t sB = (uint32_t)__cvta_generic_to_shared(&Bs[it & 1][0][0]);
        #pragma unroll
        for (int kk = 0; kk < 16; kk += 8) {
            uint32_t aa[4][4];
            #pragma unroll
            for (int ii = 0; ii < 4; ++ii)
                ldsm4(aa[ii], sA + ((ii * 16 + aRow) * 20 + kk + aCol) * 4);
            #pragma unroll
            for (int ii = 0; ii < 4; ++ii)
                #pragma unroll
                for (int r = 0; r < 4; ++r)
                    aa[ii][r] = f2tf(__uint_as_float(aa[ii][r]));
            #pragma unroll
            for (int q = 0; q < 4; ++q) {
                uint32_t bq[4];
                ldsm4(bq, sB + ((nb0 + 16 * q + bRow) * 20 + kk + bCol) * 4);
                #pragma unroll
                for (int ii = 0; ii < 4; ++ii) {
                    mma4(acc[ii][2 * q],     aa[ii], bq[0], bq[1]);
                    mma4(acc[ii][2 * q + 1], aa[ii], bq[2], bq[3]);
                }
            }
        }
        abuf = (abuf == 2) ? 0 : abuf + 1;
    }
    __syncthreads();   // before epilogue writes alias the mainloop buffers

    // Epilogue: write x1 tile to gmem AND into xs (alias).
    #pragma unroll
    for (int i = 0; i < 4; ++i) {
        long r0 = mbase + i * 16 + g;
        int lr = i * 16 + g;
        #pragma unroll
        for (int j = 0; j < 8; ++j) {
            int cn = nb0 + j * 8 + 2 * t;
            float2 v0 = make_float2(acc[i][j][0], acc[i][j][1]);
            float2 v1 = make_float2(acc[i][j][2], acc[i][j][3]);
            *(float2*)&g_x1[r0 * NST + cn]       = v0;
            *(float2*)&g_x1[(r0 + 8) * NST + cn] = v1;
            *(float2*)&xs[lr][cn]     = v0;
            *(float2*)&xs[lr + 8][cn] = v1;
        }
    }
    __syncthreads();

    // Local scan (zero init): thread k handles complex channel k.
    {
        const int k = tid;   // 0..127
        const float wc = Arot[k * 4 + 0];
        const float ws = Arot[k * 4 + 1];
        float zr = 0.f, zi = 0.f;
        #pragma unroll 8
        for (int tt = 0; tt < LC; ++tt) {
            float2 v = *(const float2*)&xs[tt][2 * k];
            float nr = fmaf(zr, wc, fmaf(-zi, ws, v.x));
            float ni = fmaf(zr, ws, fmaf( zi, wc, v.y));
            zr = nr; zi = ni;
        }
        ((float2*)g_s)[blockIdx.x * KHALF + k] = make_float2(zr, zi);
    }
}

// ===========================================================================
// K2: carry propagation, one block per batch (SMEM-staged chain).
// ===========================================================================
__global__ void __launch_bounds__(128) scan_carry(const float* __restrict__ Arot,
                                                  const float* __restrict__ x0,
                                                  float* __restrict__ tail,
                                                  int write_tail)
{
    extern __shared__ float ss[];               // [64][256]
    const int b = blockIdx.x;
    const int k = threadIdx.x;                  // 0..127

    const float4* src = (const float4*)(g_s + (size_t)b * CPB * NST);
    float4* dst = (float4*)ss;
    #pragma unroll
    for (int i = 0; i < 32; ++i)
        dst[k + i * 128] = src[k + i * 128];
    __syncthreads();

    float Wr = Arot[k * 4 + 0];
    float Wi = Arot[k * 4 + 1];
    #pragma unroll
    for (int i = 0; i < 6; ++i) {               // w -> w^64 by squaring
        float nr = Wr * Wr - Wi * Wi;
        float ni = 2.f * Wr * Wi;
        Wr = nr; Wi = ni;
    }

    float2 z = ((const float2*)x0)[b * KHALF + k];
    float zr = z.x, zi = z.y;
    #pragma unroll 8
    for (int c = 0; c < CPB; ++c) {
        ((float2*)g_in)[(b * CPB + c) * KHALF + k] = make_float2(zr, zi);
        float2 s = ((const float2*)ss)[c * KHALF + k];
        float nr = fmaf(zr, Wr, fmaf(-zi, Wi, s.x));
        float ni = fmaf(zr, Wi, fmaf( zi, Wr, s.y));
        zr = nr; zi = ni;
    }
    if (write_tail)
        ((float2*)tail)[b * KHALF + k] = make_float2(zr, zi);
}

// ===========================================================================
// K3: fused apply-scan + gemm2 (y = x @ C).
// 128 threads / 4 warps, warp tile 64x64. Scan (16-deep load batching)
// writes x tf32(rna)-rounded into xs[64][260]; mainloop ldmatrix's A from xs
// (zero CVT, zero A staging traffic), B from preconverted C^T (2-stage).
// SMEM: xs 64x260 (66560) + Bs[2][256][20] (40960) = 107520 -> 2 blocks/SM.
// ===========================================================================
__global__ void __launch_bounds__(128, 2) gemm_scan2(const float* __restrict__ Arot,
                                                     float* __restrict__ y)
{
    extern __shared__ float sm3[];
    float (*xs)[260]     = (float(*)[260])sm3;                 // 64 x 260
    float (*Bs)[256][20] = (float(*)[256][20])(sm3 + 64*260);  // [2][256][20]

    const int tid  = threadIdx.x;
    const int warp = tid >> 5;
    const int lane = tid & 31;
    const int g = lane >> 2, t = lane & 3;
    const int cid = blockIdx.x;
    const long mbase = (long)cid * 64;
    const int nb0 = warp * 64;

    const int aRow = (lane & 7) + ((lane >> 3) & 1) * 8;
    const int aCol = (lane >> 4) * 4;
    const int bRow = (lane & 7) + (lane >> 4) * 8;
    const int bCol = ((lane >> 3) & 1) * 4;

    auto commitB = [&](int k0, int st) {
        #pragma unroll
        for (int p = 0; p < 8; ++p) {
            int ch = tid + p * 128;
            int n = ch >> 2, c4 = (ch & 3) * 4;
            cp16((uint32_t)__cvta_generic_to_shared(&Bs[st][n][c4]),
                 g_Ct + n * NST + k0 + c4);
        }
        cp_commit();
    };

    commitB(0, 0);   // overlaps with the scan below

    // ---- apply-scan: gmem x1 -> recurrence -> xs (tf32-rounded) ----
    {
        const int k = tid;
        const float wc = Arot[k * 4 + 0];
        const float ws = Arot[k * 4 + 1];
        const float2* p = (const float2*)(g_x1 + (size_t)cid * LC * NST) + k;
        float2 z0 = ((const float2*)g_in)[cid * KHALF + k];
        float zr = z0.x, zi = z0.y;
        #pragma unroll
        for (int tt0 = 0; tt0 < LC; tt0 += 16) {
            float2 v[16];
            #pragma unroll
            for (int j = 0; j < 16; ++j)
                v[j] = p[(size_t)(tt0 + j) * (NST / 2)];
            #pragma unroll
            for (int j = 0; j < 16; ++j) {
                float nr = fmaf(zr, wc, fmaf(-zi, ws, v[j].x));
                float ni = fmaf(zr, ws, fmaf( zi, wc, v[j].y));
                zr = nr; zi = ni;
                *(float2*)&xs[tt0 + j][2 * k] =
                    make_float2(__uint_as_float(f2tf(zr)), __uint_as_float(f2tf(zi)));
            }
        }
    }

    // ---- mainloop: y_tile = xs @ C ----
    float acc[4][8][4];
    #pragma unroll
    for (int i = 0; i < 4; ++i)
        #pragma unroll
        for (int j = 0; j < 8; ++j)
            #pragma unroll
            for (int q = 0; q < 4; ++q) acc[i][j][q] = 0.f;

    const uint32_t sX = (uint32_t)__cvta_generic_to_shared(&xs[0][0]);

    for (int it = 0; it < 16; ++it) {
        cp_wait0();
        __syncthreads();                       // also orders scan writes (it==0)
        if (it + 1 < 16) commitB((it + 1) * 16, (it + 1) & 1);

        const int k0 = it * 16;
        const uint32_t sB = (uint32_t)__cvta_generic_to_shared(&Bs[it & 1][0][0]);
        #pragma unroll
        for (int kk = 0; kk < 16; kk += 8) {
            uint32_t aa[4][4];
            #pragma unroll
            for (int ii = 0; ii < 4; ++ii)
                ldsm4(aa[ii], sX + ((ii * 16 + aRow) * 260 + k0 + kk + aCol) * 4);
            #pragma unroll
            for (int q = 0; q < 4; ++q) {
                uint32_t bq[4];
                ldsm4(bq, sB + ((nb0 + 16 * q + bRow) * 20 + kk + bCol) * 4);
                #pragma unroll
                for (int ii = 0; ii < 4; ++ii) {
                    mma4(acc[ii][2 * q],     aa[ii], bq[0], bq[1]);
                    mma4(acc[ii][2 * q + 1], aa[ii], bq[2], bq[3]);
                }
            }
        }
    }

    #pragma unroll
    for (int i = 0; i < 4; ++i) {
        long r0 = mbase + i * 16 + g;
        #pragma unroll
        for (int j = 0; j < 8; ++j) {
            int cn = nb0 + j * 8 + 2 * t;
            *(float2*)&y[r0 * NST + cn]       = make_float2(acc[i][j][0], acc[i][j][1]);
            *(float2*)&y[(r0 + 8) * NST + cn] = make_float2(acc[i][j][2], acc[i][j][3]);
        }
    }
}

// ---------------------------------------------------------------------------
// Launch: prep -> K1 -> K2 -> K3.
// Output: y (8*4096*256 f32) then new_state (8*128*2 f32), concatenated.
// ---------------------------------------------------------------------------
extern "C" void kernel_launch(void* const* d_in, const int* in_sizes, int n_in,
                              void* d_out, int out_size)
{
    const float* u  = (const float*)d_in[0];
    const float* x0 = (const float*)d_in[1];
    const float* A  = (const float*)d_in[2];
    const float* B  = (const float*)d_in[3];
    const float* C  = (const float*)d_in[4];
    float* out = (float*)d_out;

    const int YSZ = ROWS * NST;
    const int TSZ = BATCH * KHALF * 2;
    const int wt = (out_size >= YSZ + TSZ) ? 1 : 0;
    float* tail = out + YSZ;

    const int SM1 = 66048;     // xs alias dominates (As[3]+Bs[2] = 56320)
    const int SM2 = 65536;     // ss[64][256]
    const int SM3 = 107520;    // xs[64][260] + Bs[2]

    cudaFuncSetAttribute(gemm_scan1, cudaFuncAttributeMaxDynamicSharedMemorySize, SM1);
    cudaFuncSetAttribute(scan_carry, cudaFuncAttributeMaxDynamicSharedMemorySize, SM2);
    cudaFuncSetAttribute(gemm_scan2, cudaFuncAttributeMaxDynamicSharedMemorySize, SM3);

    prep_wt<<<NST * NST / 512, 512>>>(B, C);             // tf32 transposed weights
    gemm_scan1<<<CHUNKS, 128, SM1>>>(u, A);              // x1 + chunk sums
    scan_carry<<<BATCH, 128, SM2>>>(A, x0, tail, wt);    // carries + new_state
    gemm_scan2<<<CHUNKS, 128, SM3>>>(A, out);            // x (in SMEM) @ C -> y
}